// round 2
// baseline (speedup 1.0000x reference)
#include <cuda_runtime.h>

// Problem dims
#define N_   32
#define C_   256
#define H_   56
#define W_   56
#define HW_  (H_ * W_)          // 3136
#define NP_  (N_ * HW_)         // 100352 pixels
#define TOT_ ((size_t)N_ * C_ * HW_)  // 25,690,112 elements
#define KW_CAP 2304             // max deviants per output channel (C_*9)
#define NW_  (C_ * C_ * 9)      // 589,824 weights

#define WSCAN_BLOCKS ((NW_ + 255) / 256)          // 2304
#define CSUM_THREADS (NP_ / 4)                    // 25088 (4 pixels/thread)
#define CSUM_BLOCKS  ((CSUM_THREADS + 255) / 256) // 98

// ---------------- scratch (static device memory; no allocation) -------------
__device__ float  g_s[NP_];          // per-pixel channel-sum of sign(x)
__device__ float  g_S[NP_];          // 3x3 box sum of g_s
__device__ int    g_devList[C_ * KW_CAP];
__device__ int    g_devCnt[C_];
__device__ int    g_devTotal;
__device__ double g_sumS, g_sumS2;   // base stats, shared by all channels
__device__ double g_Csum[C_], g_Scorr[C_], g_Csq[C_];
__device__ float  g_a[C_], g_b[C_];  // fused BN scale/shift

__device__ __forceinline__ float sgn(float v) {
    return (float)((v > 0.0f) - (v < 0.0f));
}

// ---------------- kernel 0: reset accumulators ------------------------------
__global__ void k_reset() {
    int t = threadIdx.x;                 // 256 threads
    g_devCnt[t] = 0;
    g_Csum[t] = 0.0; g_Scorr[t] = 0.0; g_Csq[t] = 0.0;
    if (t == 0) { g_devTotal = 0; g_sumS = 0.0; g_sumS2 = 0.0; }
}

// ---------------- kernel 1: weight scan + per-pixel channel sum (fused) -----
__global__ void __launch_bounds__(256) k_wscan_csum(const float* __restrict__ x,
                                                    const float* __restrict__ w) {
    if (blockIdx.x < WSCAN_BLOCKS) {
        // ---- weight-deviant scan ----
        int idx = blockIdx.x * 256 + threadIdx.x;
        if (idx >= NW_) return;
        float v = w[idx];
        int s = (v > 0.0f) - (v < 0.0f);     // jnp.sign
        int delta = s - 1;
        if (delta != 0) {
            int o   = idx / (C_ * 9);
            int rem = idx - o * (C_ * 9);
            int c   = rem / 9;
            int k   = rem - c * 9;
            int slot = atomicAdd(&g_devCnt[o], 1);
            g_devList[o * KW_CAP + slot] = (c << 6) | (k << 2) | (delta + 2);
            atomicAdd(&g_devTotal, 1);
        }
        return;
    }
    // ---- channel sum of sign(x), 4 pixels per thread (float4) ----
    int t = (blockIdx.x - WSCAN_BLOCKS) * 256 + threadIdx.x;
    if (t >= CSUM_THREADS) return;
    int p4 = t * 4;                          // base pixel index (same n for all 4)
    int n  = p4 / HW_;
    int hw = p4 - n * HW_;
    const float4* xp = reinterpret_cast<const float4*>(
        x + (size_t)n * C_ * HW_ + hw);
    float a0 = 0.f, a1 = 0.f, a2 = 0.f, a3 = 0.f;
#pragma unroll 8
    for (int c = 0; c < C_; c++) {
        float4 v = xp[c * (HW_ / 4)];
        a0 += sgn(v.x); a1 += sgn(v.y); a2 += sgn(v.z); a3 += sgn(v.w);
    }
    float4 r; r.x = a0; r.y = a1; r.z = a2; r.w = a3;
    *reinterpret_cast<float4*>(g_s + p4) = r;
}

// ---------------- kernel 2: 3x3 box sum + base BN stats (no FP64 hot path) --
__global__ void __launch_bounds__(256) k_box() {
    int p = blockIdx.x * blockDim.x + threadIdx.x;
    float S = 0.0f;
    if (p < NP_) {
        int n  = p / HW_;
        int hw = p - n * HW_;
        int h = hw / W_, w = hw - (hw / W_) * W_;
        const float* sp = g_s + n * HW_;
#pragma unroll
        for (int dh = -1; dh <= 1; dh++) {
            int hh = h + dh;
            if (hh < 0 || hh >= H_) continue;
#pragma unroll
            for (int dw = -1; dw <= 1; dw++) {
                int ww = w + dw;
                if (ww < 0 || ww >= W_) continue;
                S += sp[hh * W_ + ww];
            }
        }
        g_S[p] = S;
    }
    // float warp-shuffle reduction; FP64 only for one atomicAdd pair per block
    float s1 = (p < NP_) ? S : 0.0f;
    float s2 = s1 * s1;
#pragma unroll
    for (int off = 16; off > 0; off >>= 1) {
        s1 += __shfl_xor_sync(0xffffffffu, s1, off);
        s2 += __shfl_xor_sync(0xffffffffu, s2, off);
    }
    __shared__ float w1[8], w2[8];
    int lane = threadIdx.x & 31, warp = threadIdx.x >> 5;
    if (lane == 0) { w1[warp] = s1; w2[warp] = s2; }
    __syncthreads();
    if (threadIdx.x == 0) {
        float b1 = 0.f, b2 = 0.f;
#pragma unroll
        for (int i = 0; i < 8; i++) { b1 += w1[i]; b2 += w2[i]; }
        atomicAdd(&g_sumS,  (double)b1);
        atomicAdd(&g_sumS2, (double)b2);
    }
}

__device__ __forceinline__ float signx_at(const float* __restrict__ x,
                                          int n, int c, int hh, int ww) {
    if (hh < 0 || hh >= H_ || ww < 0 || ww >= W_) return 0.0f;
    float v = x[((size_t)n * C_ + c) * HW_ + hh * W_ + ww];
    return sgn(v);
}

// ---------------- kernel 3: per-channel correction stats (usually no-op) ----
__global__ void k_corrstats(const float* __restrict__ x) {
    int o = blockIdx.x;                      // one block per output channel
    int cnt = g_devCnt[o];
    if (cnt == 0) return;                    // expected hot path: exit immediately
    double c1 = 0.0, c2 = 0.0, c3 = 0.0;
    const int* list = g_devList + o * KW_CAP;
    for (int p = threadIdx.x; p < NP_; p += blockDim.x) {
        int n  = p / HW_;
        int hw = p - n * HW_;
        int h = hw / W_, w = hw - (hw / W_) * W_;
        float corr = 0.0f;
        for (int j = 0; j < cnt; j++) {
            int e = list[j];
            int c = e >> 6;
            int k = (e >> 2) & 15;
            float delta = (float)((e & 3) - 2);
            int dh = k / 3 - 1, dw = k % 3 - 1;
            corr += delta * signx_at(x, n, c, h + dh, w + dw);
        }
        c1 += (double)corr;
        c2 += (double)g_S[p] * (double)corr;
        c3 += (double)corr * (double)corr;
    }
    __shared__ double s1[256], s2[256], s3[256];
    int t = threadIdx.x;
    s1[t] = c1; s2[t] = c2; s3[t] = c3;
    __syncthreads();
    for (int off = 128; off > 0; off >>= 1) {
        if (t < off) { s1[t] += s1[t+off]; s2[t] += s2[t+off]; s3[t] += s3[t+off]; }
        __syncthreads();
    }
    if (t == 0) { g_Csum[o] = s1[0]; g_Scorr[o] = s2[0]; g_Csq[o] = s3[0]; }
}

// ---------------- kernel 4: fuse BN params ----------------------------------
__global__ void k_params(const float* __restrict__ gamma,
                         const float* __restrict__ beta) {
    int c = threadIdx.x;                     // 256 threads
    const double M = (double)NP_;
    double mean = (g_sumS + g_Csum[c]) / M;
    double ex2  = (g_sumS2 + 2.0 * g_Scorr[c] + g_Csq[c]) / M;
    double var  = ex2 - mean * mean;
    float a = gamma[c] * (float)(1.0 / sqrt(var + 1e-5));
    g_a[c] = a;
    g_b[c] = beta[c] - a * (float)mean;
}

// ---------------- kernel 5: normalize + residual (vectorized x4) ------------
__global__ void __launch_bounds__(256) k_out(const float* __restrict__ x,
                                             float* __restrict__ out) {
    size_t t = (size_t)blockIdx.x * blockDim.x + threadIdx.x;
    size_t idx = t * 4;
    if (idx >= TOT_) return;
    int hw = (int)(idx % HW_);               // HW_ % 4 == 0 -> vector stays in-row
    size_t nc = idx / HW_;
    int c = (int)(nc % C_);
    int n = (int)(nc / C_);
    int p = n * HW_ + hw;

    float4 xs = *reinterpret_cast<const float4*>(x + idx);
    float4 Ss = *reinterpret_cast<const float4*>(g_S + p);
    float a = g_a[c], b = g_b[c];

    if (g_devTotal != 0) {                   // rare slow path
        int cnt = g_devCnt[c];
        if (cnt != 0) {
            const int* list = g_devList + c * KW_CAP;
            int h = hw / W_, w0 = hw - (hw / W_) * W_;
            float corr[4] = {0.f, 0.f, 0.f, 0.f};
            for (int j = 0; j < cnt; j++) {
                int e = list[j];
                int cc = e >> 6;
                int k  = (e >> 2) & 15;
                float delta = (float)((e & 3) - 2);
                int dh = k / 3 - 1, dw = k % 3 - 1;
#pragma unroll
                for (int l = 0; l < 4; l++)
                    corr[l] += delta * signx_at(x, n, cc, h + dh, w0 + l + dw);
            }
            Ss.x += corr[0]; Ss.y += corr[1]; Ss.z += corr[2]; Ss.w += corr[3];
        }
    }

    float4 o4;
    o4.x = fmaf(a, Ss.x, b) + xs.x;
    o4.y = fmaf(a, Ss.y, b) + xs.y;
    o4.z = fmaf(a, Ss.z, b) + xs.z;
    o4.w = fmaf(a, Ss.w, b) + xs.w;
    *reinterpret_cast<float4*>(out + idx) = o4;
}

// ---------------- launch -----------------------------------------------------
extern "C" void kernel_launch(void* const* d_in, const int* in_sizes, int n_in,
                              void* d_out, int out_size) {
    const float* x     = (const float*)d_in[0];
    const float* w     = (const float*)d_in[1];
    const float* gamma = (const float*)d_in[2];
    const float* beta  = (const float*)d_in[3];
    float* out = (float*)d_out;

    k_reset<<<1, 256>>>();
    k_wscan_csum<<<WSCAN_BLOCKS + CSUM_BLOCKS, 256>>>(x, w);
    k_box<<<(NP_ + 255) / 256, 256>>>();
    k_corrstats<<<C_, 256>>>(x);
    k_params<<<1, 256>>>(gamma, beta);
    k_out<<<(unsigned)((TOT_ / 4 + 255) / 256), 256>>>(x, out);
}

// round 3
// speedup vs baseline: 1.4042x; 1.4042x over previous
#include <cuda_runtime.h>

// Problem dims
#define N_   32
#define C_   256
#define H_   56
#define W_   56
#define HW_  (H_ * W_)          // 3136
#define NP_  (N_ * HW_)         // 100352 pixels
#define QUADS (NP_ / 4)         // 25088 pixel-quads
#define TOT_ ((size_t)N_ * C_ * HW_)  // 25,690,112 elements
#define KW_CAP 2304             // max deviants per output channel (C_*9)
#define NW_  (C_ * C_ * 9)      // 589,824 weights

#define CCHUNKS 4               // channel chunks in csum (64 ch each)
#define OCHUNK  8               // channels per thread in k_out

// ---------------- scratch (static device memory; no allocation) -------------
__device__ float  g_s[NP_];          // per-pixel channel-sum of sign(x)
__device__ float  g_S[NP_];          // 3x3 box sum of g_s
__device__ int    g_devList[C_ * KW_CAP];
__device__ int    g_devCnt[C_];
__device__ int    g_devTotal;
__device__ double g_sumS, g_sumS2;   // base stats, shared by all channels
__device__ double g_Csum[C_], g_Scorr[C_], g_Csq[C_];
__device__ float  g_a[C_], g_b[C_];  // fused BN scale/shift

__device__ __forceinline__ float sgn(float v) {
    return (float)((v > 0.0f) - (v < 0.0f));
}

// ---------------- kernel 0: reset accumulators + zero g_s -------------------
__global__ void __launch_bounds__(256) k_reset() {
    int p = blockIdx.x * 256 + threadIdx.x;
    if (p < NP_) g_s[p] = 0.0f;
    if (blockIdx.x == 0) {
        int t = threadIdx.x;             // 256 threads == C_
        g_devCnt[t] = 0;
        g_Csum[t] = 0.0; g_Scorr[t] = 0.0; g_Csq[t] = 0.0;
        if (t == 0) { g_devTotal = 0; g_sumS = 0.0; g_sumS2 = 0.0; }
    }
}

// ---------------- kernel 1: scan weights for sign(w) != +1 ------------------
__global__ void __launch_bounds__(256) k_wscan(const float* __restrict__ w) {
    int idx = blockIdx.x * 256 + threadIdx.x;
    if (idx >= NW_) return;
    float v = w[idx];
    int s = (v > 0.0f) - (v < 0.0f);     // jnp.sign
    int delta = s - 1;                   // deviation from all-ones base
    if (delta != 0) {
        int o   = idx / (C_ * 9);
        int rem = idx - o * (C_ * 9);
        int c   = rem / 9;
        int k   = rem - c * 9;
        int slot = atomicAdd(&g_devCnt[o], 1);
        g_devList[o * KW_CAP + slot] = (c << 6) | (k << 2) | (delta + 2);
        atomicAdd(&g_devTotal, 1);
    }
}

// ---------------- kernel 2: per-pixel channel sum of sign(x) ----------------
// grid (QUADS/256, CCHUNKS): each thread sums 64 channels of one pixel-quad,
// accumulates into g_s via float atomics (exact: integer-valued floats).
__global__ void __launch_bounds__(256) k_csum(const float* __restrict__ x) {
    int q = blockIdx.x * 256 + threadIdx.x;      // pixel-quad index
    if (q >= QUADS) return;
    int c0 = blockIdx.y * (C_ / CCHUNKS);        // 64-channel chunk
    int p4 = q * 4;
    int n  = p4 / HW_;
    int hw = p4 - n * HW_;
    const float4* xp = reinterpret_cast<const float4*>(
        x + ((size_t)n * C_ + c0) * HW_ + hw);
    float a0 = 0.f, a1 = 0.f, a2 = 0.f, a3 = 0.f;
#pragma unroll 8
    for (int c = 0; c < C_ / CCHUNKS; c++) {
        float4 v = xp[c * (HW_ / 4)];
        a0 += sgn(v.x); a1 += sgn(v.y); a2 += sgn(v.z); a3 += sgn(v.w);
    }
    atomicAdd(&g_s[p4 + 0], a0);
    atomicAdd(&g_s[p4 + 1], a1);
    atomicAdd(&g_s[p4 + 2], a2);
    atomicAdd(&g_s[p4 + 3], a3);
}

// ---------------- kernel 3: 3x3 box sum + base BN stats (float reduce) ------
__global__ void __launch_bounds__(256) k_box() {
    int p = blockIdx.x * blockDim.x + threadIdx.x;
    float S = 0.0f;
    if (p < NP_) {
        int n  = p / HW_;
        int hw = p - n * HW_;
        int h = hw / W_, w = hw - (hw / W_) * W_;
        const float* sp = g_s + n * HW_;
#pragma unroll
        for (int dh = -1; dh <= 1; dh++) {
            int hh = h + dh;
            if (hh < 0 || hh >= H_) continue;
#pragma unroll
            for (int dw = -1; dw <= 1; dw++) {
                int ww = w + dw;
                if (ww < 0 || ww >= W_) continue;
                S += sp[hh * W_ + ww];
            }
        }
        g_S[p] = S;
    }
    float s1 = (p < NP_) ? S : 0.0f;
    float s2 = s1 * s1;
#pragma unroll
    for (int off = 16; off > 0; off >>= 1) {
        s1 += __shfl_xor_sync(0xffffffffu, s1, off);
        s2 += __shfl_xor_sync(0xffffffffu, s2, off);
    }
    __shared__ float w1[8], w2[8];
    int lane = threadIdx.x & 31, warp = threadIdx.x >> 5;
    if (lane == 0) { w1[warp] = s1; w2[warp] = s2; }
    __syncthreads();
    if (threadIdx.x == 0) {
        float b1 = 0.f, b2 = 0.f;
#pragma unroll
        for (int i = 0; i < 8; i++) { b1 += w1[i]; b2 += w2[i]; }
        atomicAdd(&g_sumS,  (double)b1);
        atomicAdd(&g_sumS2, (double)b2);
    }
}

__device__ __forceinline__ float signx_at(const float* __restrict__ x,
                                          int n, int c, int hh, int ww) {
    if (hh < 0 || hh >= H_ || ww < 0 || ww >= W_) return 0.0f;
    float v = x[((size_t)n * C_ + c) * HW_ + hh * W_ + ww];
    return sgn(v);
}

// ---------------- kernel 4: per-channel correction stats (usually no-op) ----
__global__ void k_corrstats(const float* __restrict__ x) {
    int o = blockIdx.x;                      // one block per output channel
    int cnt = g_devCnt[o];
    if (cnt == 0) return;                    // expected hot path
    double c1 = 0.0, c2 = 0.0, c3 = 0.0;
    const int* list = g_devList + o * KW_CAP;
    for (int p = threadIdx.x; p < NP_; p += blockDim.x) {
        int n  = p / HW_;
        int hw = p - n * HW_;
        int h = hw / W_, w = hw - (hw / W_) * W_;
        float corr = 0.0f;
        for (int j = 0; j < cnt; j++) {
            int e = list[j];
            int c = e >> 6;
            int k = (e >> 2) & 15;
            float delta = (float)((e & 3) - 2);
            int dh = k / 3 - 1, dw = k % 3 - 1;
            corr += delta * signx_at(x, n, c, h + dh, w + dw);
        }
        c1 += (double)corr;
        c2 += (double)g_S[p] * (double)corr;
        c3 += (double)corr * (double)corr;
    }
    __shared__ double s1[256], s2[256], s3[256];
    int t = threadIdx.x;
    s1[t] = c1; s2[t] = c2; s3[t] = c3;
    __syncthreads();
    for (int off = 128; off > 0; off >>= 1) {
        if (t < off) { s1[t] += s1[t+off]; s2[t] += s2[t+off]; s3[t] += s3[t+off]; }
        __syncthreads();
    }
    if (t == 0) { g_Csum[o] = s1[0]; g_Scorr[o] = s2[0]; g_Csq[o] = s3[0]; }
}

// ---------------- kernel 5: fuse BN params ----------------------------------
__global__ void k_params(const float* __restrict__ gamma,
                         const float* __restrict__ beta) {
    int c = threadIdx.x;                     // 256 threads
    const double M = (double)NP_;
    double mean = (g_sumS + g_Csum[c]) / M;
    double ex2  = (g_sumS2 + 2.0 * g_Scorr[c] + g_Csq[c]) / M;
    double var  = ex2 - mean * mean;
    float a = gamma[c] * (float)(1.0 / sqrt(var + 1e-5));
    g_a[c] = a;
    g_b[c] = beta[c] - a * (float)mean;
}

// ---------------- kernel 6: normalize + residual -----------------------------
// grid (QUADS/256, C_/OCHUNK): each thread loads g_S once and serves OCHUNK
// channels -> 8x less g_S traffic, high block count.
__global__ void __launch_bounds__(256) k_out(const float* __restrict__ x,
                                             float* __restrict__ out) {
    int q = blockIdx.x * 256 + threadIdx.x;
    if (q >= QUADS) return;
    int c0 = blockIdx.y * OCHUNK;
    int p4 = q * 4;
    int n  = p4 / HW_;
    int hw = p4 - n * HW_;

    float4 Ss = *reinterpret_cast<const float4*>(g_S + p4);
    const int devTotal = g_devTotal;

    size_t base = ((size_t)n * C_ + c0) * HW_ + hw;
#pragma unroll
    for (int cc = 0; cc < OCHUNK; cc++) {
        int c = c0 + cc;
        float a = g_a[c], b = g_b[c];
        float4 Sc = Ss;

        if (devTotal != 0) {                 // rare slow path
            int cnt = g_devCnt[c];
            if (cnt != 0) {
                const int* list = g_devList + c * KW_CAP;
                int h = hw / W_, w0 = hw - (hw / W_) * W_;
                float corr[4] = {0.f, 0.f, 0.f, 0.f};
                for (int j = 0; j < cnt; j++) {
                    int e = list[j];
                    int cin = e >> 6;
                    int k   = (e >> 2) & 15;
                    float delta = (float)((e & 3) - 2);
                    int dh = k / 3 - 1, dw = k % 3 - 1;
#pragma unroll
                    for (int l = 0; l < 4; l++)
                        corr[l] += delta * signx_at(x, n, cin, h + dh, w0 + l + dw);
                }
                Sc.x += corr[0]; Sc.y += corr[1]; Sc.z += corr[2]; Sc.w += corr[3];
            }
        }

        size_t idx = base + (size_t)cc * HW_;
        float4 xs = *reinterpret_cast<const float4*>(x + idx);
        float4 o4;
        o4.x = fmaf(a, Sc.x, b) + xs.x;
        o4.y = fmaf(a, Sc.y, b) + xs.y;
        o4.z = fmaf(a, Sc.z, b) + xs.z;
        o4.w = fmaf(a, Sc.w, b) + xs.w;
        *reinterpret_cast<float4*>(out + idx) = o4;
    }
}

// ---------------- launch -----------------------------------------------------
extern "C" void kernel_launch(void* const* d_in, const int* in_sizes, int n_in,
                              void* d_out, int out_size) {
    const float* x     = (const float*)d_in[0];
    const float* w     = (const float*)d_in[1];
    const float* gamma = (const float*)d_in[2];
    const float* beta  = (const float*)d_in[3];
    float* out = (float*)d_out;

    k_reset<<<(NP_ + 255) / 256, 256>>>();
    k_wscan<<<(NW_ + 255) / 256, 256>>>(w);
    {
        dim3 grid((QUADS + 255) / 256, CCHUNKS);
        k_csum<<<grid, 256>>>(x);
    }
    k_box<<<(NP_ + 255) / 256, 256>>>();
    k_corrstats<<<C_, 256>>>(x);
    k_params<<<1, 256>>>(gamma, beta);
    {
        dim3 grid((QUADS + 255) / 256, C_ / OCHUNK);
        k_out<<<grid, 256>>>(x, out);
    }
}